// round 6
// baseline (speedup 1.0000x reference)
#include <cuda_runtime.h>
#include <cuda_fp16.h>

#define MAXN   200000
#define CIN    32
#define HID    192
#define KOFF   9
#define COUT   32
#define EPSV   1e-5f

// fp16 scratch: expanded activations x1 = relu6(bn1(feats@W1))  [N,192]
// and depthwise output z = relu6(bn2(dwconv(x1)))               [N,192]
// 76.8 MB each -> x1 fits in L2 (126MB) so the random gather stays L2-resident.
__device__ __half g_x1[(size_t)MAXN * HID];
__device__ __half g_z [(size_t)MAXN * HID];

__device__ __forceinline__ float relu6f(float x) {
    return fminf(fmaxf(x, 0.0f), 6.0f);
}
__device__ __forceinline__ float2 h2tof2(unsigned int u) {
    __half2 h = *reinterpret_cast<__half2*>(&u);
    return __half22float2(h);
}
__device__ __forceinline__ unsigned int f2toh2(float a, float b) {
    __half2 h = __floats2half2_rn(a, b);
    return *reinterpret_cast<unsigned int*>(&h);
}

// ---------------------------------------------------------------------------
// Kernel 1: expand 1x1 conv + BN1 + relu6 -> g_x1 (fp16)
// 192 threads = one thread per hidden channel. W1 column (32 floats) lives in
// registers; BN folded into (s1,c1). feats staged 8 rows at a time in smem.
// ---------------------------------------------------------------------------
__global__ void __launch_bounds__(192) k_expand(
    const float* __restrict__ feats, const float* __restrict__ W1,
    const float* __restrict__ g1, const float* __restrict__ b1,
    const float* __restrict__ m1, const float* __restrict__ v1,
    int N, int rowblocks)
{
    __shared__ __align__(16) float sf[8 * CIN];
    const int h = threadIdx.x;

    float w[CIN];
#pragma unroll
    for (int i = 0; i < CIN; i++) w[i] = W1[i * HID + h];

    const float s1 = g1[h] * rsqrtf(v1[h] + EPSV);
    const float c1 = b1[h] - m1[h] * s1;

    for (int rb = blockIdx.x; rb < rowblocks; rb += gridDim.x) {
        const int r0 = rb * 8;
        // stage 8 rows x 32 feats
        for (int j = h; j < 8 * CIN; j += 192) {
            const int r = j >> 5, i = j & 31;
            const int row = r0 + r;
            sf[j] = (row < N) ? feats[row * CIN + i] : 0.0f;
        }
        __syncthreads();

#pragma unroll
        for (int r = 0; r < 8; r++) {
            const float4* fp = reinterpret_cast<const float4*>(sf + r * CIN);
            float acc = 0.0f;
#pragma unroll
            for (int i4 = 0; i4 < 8; i4++) {
                const float4 f = fp[i4];
                acc = fmaf(f.x, w[4 * i4 + 0], acc);
                acc = fmaf(f.y, w[4 * i4 + 1], acc);
                acc = fmaf(f.z, w[4 * i4 + 2], acc);
                acc = fmaf(f.w, w[4 * i4 + 3], acc);
            }
            const int row = r0 + r;
            if (row < N) {
                const float y = relu6f(fmaf(acc, s1, c1));
                g_x1[(size_t)row * HID + h] = __float2half(y);
            }
        }
        __syncthreads();
    }
}

// ---------------------------------------------------------------------------
// Kernel 2: depthwise sparse conv (9-way gather) + BN2 + relu6 -> g_z (fp16)
// Thread = (4 rows, one 8-channel chunk). 24 chunks cover the 192 channels.
// All 9 gathers per (row,chunk) are independent LDG.128 -> MLP to hide L2 lat.
// W2 chunk loaded once per k and reused across the 4 rows.
// ---------------------------------------------------------------------------
__global__ void __launch_bounds__(256) k_dw(
    const int* __restrict__ nbr, const float* __restrict__ W2,
    const float* __restrict__ g2, const float* __restrict__ b2,
    const float* __restrict__ m2, const float* __restrict__ v2,
    int N)
{
    __shared__ __align__(16) float W2s[KOFF * HID];
    __shared__ __align__(16) float s2s[HID];
    __shared__ __align__(16) float c2s[HID];

    const int tid = threadIdx.x;
    for (int t = tid; t < KOFF * HID; t += 256) W2s[t] = W2[t];
    for (int t = tid; t < HID; t += 256) {
        const float s = g2[t] * rsqrtf(v2[t] + EPSV);
        s2s[t] = s;
        c2s[t] = b2[t] - m2[t] * s;
    }
    __syncthreads();

    const long long gidx = (long long)blockIdx.x * 256 + tid;
    const int chunk = (int)(gidx % 24);       // 8 channels per chunk
    const int rg    = (int)(gidx / 24);
    const int r0    = rg * 4;
    if (r0 >= N) return;
    const int nrows = (N - r0 < 4) ? (N - r0) : 4;
    const int ch8 = chunk * 8;

    int idxs[4][KOFF];
#pragma unroll
    for (int r = 0; r < 4; r++)
#pragma unroll
        for (int k = 0; k < KOFF; k++)
            idxs[r][k] = (r < nrows) ? nbr[(r0 + r) * KOFF + k] : -1;

    float2 acc[4][4];
#pragma unroll
    for (int r = 0; r < 4; r++)
#pragma unroll
        for (int j = 0; j < 4; j++) acc[r][j] = make_float2(0.0f, 0.0f);

    const uint4* xb = reinterpret_cast<const uint4*>(g_x1);

#pragma unroll
    for (int k = 0; k < KOFF; k++) {
        const float4 wA = *reinterpret_cast<const float4*>(W2s + k * HID + ch8);
        const float4 wB = *reinterpret_cast<const float4*>(W2s + k * HID + ch8 + 4);
#pragma unroll
        for (int r = 0; r < 4; r++) {
            const int id = idxs[r][k];
            if (id >= 0) {
                const uint4 v = xb[id * 24 + chunk];
                const float2 f0 = h2tof2(v.x);
                const float2 f1 = h2tof2(v.y);
                const float2 f2 = h2tof2(v.z);
                const float2 f3 = h2tof2(v.w);
                acc[r][0].x = fmaf(f0.x, wA.x, acc[r][0].x);
                acc[r][0].y = fmaf(f0.y, wA.y, acc[r][0].y);
                acc[r][1].x = fmaf(f1.x, wA.z, acc[r][1].x);
                acc[r][1].y = fmaf(f1.y, wA.w, acc[r][1].y);
                acc[r][2].x = fmaf(f2.x, wB.x, acc[r][2].x);
                acc[r][2].y = fmaf(f2.y, wB.y, acc[r][2].y);
                acc[r][3].x = fmaf(f3.x, wB.z, acc[r][3].x);
                acc[r][3].y = fmaf(f3.y, wB.w, acc[r][3].y);
            }
        }
    }

    const float4 sA = *reinterpret_cast<const float4*>(s2s + ch8);
    const float4 sB = *reinterpret_cast<const float4*>(s2s + ch8 + 4);
    const float4 cA = *reinterpret_cast<const float4*>(c2s + ch8);
    const float4 cB = *reinterpret_cast<const float4*>(c2s + ch8 + 4);
    uint4* zb = reinterpret_cast<uint4*>(g_z);

#pragma unroll
    for (int r = 0; r < 4; r++) {
        if (r < nrows) {
            const float y0 = relu6f(fmaf(acc[r][0].x, sA.x, cA.x));
            const float y1 = relu6f(fmaf(acc[r][0].y, sA.y, cA.y));
            const float y2 = relu6f(fmaf(acc[r][1].x, sA.z, cA.z));
            const float y3 = relu6f(fmaf(acc[r][1].y, sA.w, cA.w));
            const float y4 = relu6f(fmaf(acc[r][2].x, sB.x, cB.x));
            const float y5 = relu6f(fmaf(acc[r][2].y, sB.y, cB.y));
            const float y6 = relu6f(fmaf(acc[r][3].x, sB.z, cB.z));
            const float y7 = relu6f(fmaf(acc[r][3].y, sB.w, cB.w));
            uint4 o;
            o.x = f2toh2(y0, y1);
            o.y = f2toh2(y2, y3);
            o.z = f2toh2(y4, y5);
            o.w = f2toh2(y6, y7);
            zb[(r0 + r) * 24 + chunk] = o;
        }
    }
}

// ---------------------------------------------------------------------------
// Kernel 3: project 1x1 conv (z @ W3) + BN3 + residual -> out (fp32)
// 64-row tile. z staged in smem with stride 196 (bank-conflict-free), W3 in
// smem. Each thread computes a 2-row x 4-col micro-tile (LDS.128 on W3).
// ---------------------------------------------------------------------------
#define ZS_STRIDE 196
#define SMEM3_FLOATS (HID * COUT + 64 * ZS_STRIDE)
#define SMEM3_BYTES  (SMEM3_FLOATS * 4)

extern __shared__ __align__(16) float smem3[];

__global__ void __launch_bounds__(256, 2) k_proj(
    const float* __restrict__ W3, const float* __restrict__ feats,
    const float* __restrict__ g3, const float* __restrict__ b3,
    const float* __restrict__ m3, const float* __restrict__ v3,
    float* __restrict__ out, int N)
{
    float* W3s = smem3;                 // 192*32 floats
    float* zs  = smem3 + HID * COUT;    // 64 * 196 floats

    const int tid = threadIdx.x;
    for (int t = tid; t < HID * COUT; t += 256) W3s[t] = W3[t];

    const int r0 = blockIdx.x * 64;
    const uint4* zb = reinterpret_cast<const uint4*>(g_z);

    // stage z tile: 64 rows x 24 chunks = 1536 items = 6 per thread
#pragma unroll
    for (int it = 0; it < 6; it++) {
        const int item = tid + it * 256;
        const int r = item / 24, ch = item % 24;
        const int row = r0 + r;
        float4 a, b;
        if (row < N) {
            const uint4 v = zb[row * 24 + ch];
            const float2 f0 = h2tof2(v.x);
            const float2 f1 = h2tof2(v.y);
            const float2 f2 = h2tof2(v.z);
            const float2 f3 = h2tof2(v.w);
            a = make_float4(f0.x, f0.y, f1.x, f1.y);
            b = make_float4(f2.x, f2.y, f3.x, f3.y);
        } else {
            a = make_float4(0.f, 0.f, 0.f, 0.f);
            b = a;
        }
        *reinterpret_cast<float4*>(zs + r * ZS_STRIDE + ch * 8)     = a;
        *reinterpret_cast<float4*>(zs + r * ZS_STRIDE + ch * 8 + 4) = b;
    }
    __syncthreads();

    // micro-tile: 2 rows x 4 cols per thread
    const int rgp = tid >> 3;            // 0..31 -> rows 2*rgp, 2*rgp+1
    const int c0  = (tid & 7) * 4;       // 0..28

    float acc00 = 0.f, acc01 = 0.f, acc02 = 0.f, acc03 = 0.f;
    float acc10 = 0.f, acc11 = 0.f, acc12 = 0.f, acc13 = 0.f;

    const float* z0 = zs + (2 * rgp) * ZS_STRIDE;
    const float* z1 = z0 + ZS_STRIDE;

#pragma unroll 4
    for (int h = 0; h < HID; h++) {
        const float a0 = z0[h];
        const float a1 = z1[h];
        const float4 wv = *reinterpret_cast<const float4*>(W3s + h * COUT + c0);
        acc00 = fmaf(a0, wv.x, acc00);
        acc01 = fmaf(a0, wv.y, acc01);
        acc02 = fmaf(a0, wv.z, acc02);
        acc03 = fmaf(a0, wv.w, acc03);
        acc10 = fmaf(a1, wv.x, acc10);
        acc11 = fmaf(a1, wv.y, acc11);
        acc12 = fmaf(a1, wv.z, acc12);
        acc13 = fmaf(a1, wv.w, acc13);
    }

    // BN3 fold for the 4 output channels
    const float4 gg = *reinterpret_cast<const float4*>(g3 + c0);
    const float4 bb = *reinterpret_cast<const float4*>(b3 + c0);
    const float4 mm = *reinterpret_cast<const float4*>(m3 + c0);
    const float4 vv = *reinterpret_cast<const float4*>(v3 + c0);
    const float s0 = gg.x * rsqrtf(vv.x + EPSV);
    const float s1 = gg.y * rsqrtf(vv.y + EPSV);
    const float s2 = gg.z * rsqrtf(vv.z + EPSV);
    const float s3 = gg.w * rsqrtf(vv.w + EPSV);
    const float d0 = bb.x - mm.x * s0;
    const float d1 = bb.y - mm.y * s1;
    const float d2 = bb.z - mm.z * s2;
    const float d3 = bb.w - mm.w * s3;

    const int row = r0 + 2 * rgp;
    if (row < N) {
        const float4 fi = *reinterpret_cast<const float4*>(feats + row * COUT + c0);
        float4 o;
        o.x = fmaf(acc00, s0, d0) + fi.x;
        o.y = fmaf(acc01, s1, d1) + fi.y;
        o.z = fmaf(acc02, s2, d2) + fi.z;
        o.w = fmaf(acc03, s3, d3) + fi.w;
        *reinterpret_cast<float4*>(out + row * COUT + c0) = o;
    }
    if (row + 1 < N) {
        const float4 fi = *reinterpret_cast<const float4*>(feats + (row + 1) * COUT + c0);
        float4 o;
        o.x = fmaf(acc10, s0, d0) + fi.x;
        o.y = fmaf(acc11, s1, d1) + fi.y;
        o.z = fmaf(acc12, s2, d2) + fi.z;
        o.w = fmaf(acc13, s3, d3) + fi.w;
        *reinterpret_cast<float4*>(out + (row + 1) * COUT + c0) = o;
    }
}

// ---------------------------------------------------------------------------
extern "C" void kernel_launch(void* const* d_in, const int* in_sizes, int n_in,
                              void* d_out, int out_size)
{
    const float* feats = (const float*)d_in[0];
    const int*   nbr   = (const int*)  d_in[1];
    const float* W1    = (const float*)d_in[2];
    const float* W2    = (const float*)d_in[3];
    const float* W3    = (const float*)d_in[4];
    const float* g1 = (const float*)d_in[5],  *b1 = (const float*)d_in[6];
    const float* m1 = (const float*)d_in[7],  *v1 = (const float*)d_in[8];
    const float* g2 = (const float*)d_in[9],  *b2 = (const float*)d_in[10];
    const float* m2 = (const float*)d_in[11], *v2 = (const float*)d_in[12];
    const float* g3 = (const float*)d_in[13], *b3 = (const float*)d_in[14];
    const float* m3 = (const float*)d_in[15], *v3 = (const float*)d_in[16];
    float* out = (float*)d_out;

    int N = in_sizes[0] / CIN;
    if (N > MAXN) N = MAXN;

    // K1: expand
    const int rowblocks = (N + 7) / 8;
    int grid1 = rowblocks < 1480 ? rowblocks : 1480;
    k_expand<<<grid1, 192>>>(feats, W1, g1, b1, m1, v1, N, rowblocks);

    // K2: depthwise gather
    const long long items = (long long)((N + 3) / 4) * 24;
    const int grid2 = (int)((items + 255) / 256);
    k_dw<<<grid2, 256>>>(nbr, W2, g2, b2, m2, v2, N);

    // K3: project + residual (needs >48KB dynamic smem)
    cudaFuncSetAttribute(k_proj, cudaFuncAttributeMaxDynamicSharedMemorySize,
                         SMEM3_BYTES);
    const int grid3 = (N + 63) / 64;
    k_proj<<<grid3, 256, SMEM3_BYTES>>>(W3, feats, g3, b3, m3, v3, out, N);
}

// round 9
// speedup vs baseline: 1.5343x; 1.5343x over previous
#include <cuda_runtime.h>
#include <cuda_fp16.h>

#define MAXN   200000
#define CIN    32
#define HID    192
#define KOFF   9
#define COUT   32
#define EPSV   1e-5f

// fp16 scratch: expanded activations x1 = relu6(bn1(feats@W1))  [N,192]
// and depthwise output z = relu6(bn2(dwconv(x1)))               [N,192]
// 76.8 MB each -> x1/z stay mostly L2-resident (126MB L2).
__device__ __half g_x1[(size_t)MAXN * HID];
__device__ __half g_z [(size_t)MAXN * HID];

__device__ __forceinline__ float relu6f(float x) {
    return fminf(fmaxf(x, 0.0f), 6.0f);
}
__device__ __forceinline__ float2 h2tof2(unsigned int u) {
    __half2 h = *reinterpret_cast<__half2*>(&u);
    return __half22float2(h);
}
__device__ __forceinline__ unsigned int f2toh2(float a, float b) {
    __half2 h = __floats2half2_rn(a, b);
    return *reinterpret_cast<unsigned int*>(&h);
}
__device__ __forceinline__ unsigned int packh(__half lo, __half hi) {
    __half2 h = __halves2half2(lo, hi);
    return *reinterpret_cast<unsigned int*>(&h);
}

// m16n8k16 fp16 x fp16 -> fp32 MMA
__device__ __forceinline__ void mma16816(
    float& d0, float& d1, float& d2, float& d3,
    unsigned a0, unsigned a1, unsigned a2, unsigned a3,
    unsigned b0, unsigned b1)
{
    asm volatile(
        "mma.sync.aligned.m16n8k16.row.col.f32.f16.f16.f32 "
        "{%0,%1,%2,%3}, {%4,%5,%6,%7}, {%8,%9}, {%0,%1,%2,%3};\n"
        : "+f"(d0), "+f"(d1), "+f"(d2), "+f"(d3)
        : "r"(a0), "r"(a1), "r"(a2), "r"(a3), "r"(b0), "r"(b1));
}

// ---------------------------------------------------------------------------
// Kernel 1 (MMA): expand 1x1 conv + BN1 + relu6 -> g_x1 (fp16)
// Block = 768 thr = 24 warps; warp w owns output cols [8w, 8w+8).
// 64-row tile: feats staged fp16 in smem (stride 40 halves = 20 words,
// 20 mod 32 -> conflict-free fragment loads). K=32 -> 2 k-steps; W1
// B-fragments in 4 regs/thread. Epilogue via smem so g_x1 store is uint4.
// ---------------------------------------------------------------------------
#define FST   40     // feats smem row stride (halves) — conflict-free
#define XST   208    // x1 out smem row stride (halves), 416B = 26 uint4

__global__ void __launch_bounds__(768) k_expand(
    const float* __restrict__ feats, const float* __restrict__ W1,
    const float* __restrict__ g1, const float* __restrict__ b1,
    const float* __restrict__ m1, const float* __restrict__ v1,
    int N)
{
    __shared__ __align__(16) __half sf[64 * FST];
    __shared__ __align__(16) __half sx[64 * XST];

    const int tid  = threadIdx.x;
    const int w    = tid >> 5;          // 0..23 : n-tile
    const int lane = tid & 31;
    const int g    = lane >> 2;
    const int t    = lane & 3;
    const int colb = w * 8;
    const int c0   = colb + 2 * t;
    const int c1   = c0 + 1;

    // B fragments: reg0 covers k rows {k0,k0+1}, reg1 rows {k0+8,k0+9}, col colb+g
    unsigned bf[2][2];
#pragma unroll
    for (int s = 0; s < 2; s++) {
        const int col = colb + g;
        const int k0 = 16 * s + 2 * t;
        bf[s][0] = packh(__float2half(W1[(k0)     * HID + col]),
                         __float2half(W1[(k0 + 1) * HID + col]));
        bf[s][1] = packh(__float2half(W1[(k0 + 8) * HID + col]),
                         __float2half(W1[(k0 + 9) * HID + col]));
    }
    const float s_a = g1[c0] * rsqrtf(v1[c0] + EPSV);
    const float o_a = b1[c0] - m1[c0] * s_a;
    const float s_b = g1[c1] * rsqrtf(v1[c1] + EPSV);
    const float o_b = b1[c1] - m1[c1] * s_b;

    const int r0 = blockIdx.x * 64;

    // stage 64 rows x 32 feats (fp32 -> fp16)
#pragma unroll
    for (int i = tid; i < 64 * CIN; i += 768) {
        const int r = i >> 5, c = i & 31;
        const int row = r0 + r;
        const float v = (row < N) ? feats[row * CIN + c] : 0.0f;
        sf[r * FST + c] = __float2half(v);
    }
    __syncthreads();

#pragma unroll
    for (int sub = 0; sub < 4; sub++) {
        float d0 = 0.f, d1 = 0.f, d2 = 0.f, d3 = 0.f;
        const __half* base = sf + (sub * 16) * FST;
#pragma unroll
        for (int s = 0; s < 2; s++) {
            const int ko = 2 * t + 16 * s;
            unsigned a0 = *reinterpret_cast<const unsigned*>(base + g * FST + ko);
            unsigned a1 = *reinterpret_cast<const unsigned*>(base + (g + 8) * FST + ko);
            unsigned a2 = *reinterpret_cast<const unsigned*>(base + g * FST + ko + 8);
            unsigned a3 = *reinterpret_cast<const unsigned*>(base + (g + 8) * FST + ko + 8);
            mma16816(d0, d1, d2, d3, a0, a1, a2, a3, bf[s][0], bf[s][1]);
        }
        const int rlo = sub * 16 + g;
        const int rhi = rlo + 8;
        const float y0 = relu6f(fmaf(d0, s_a, o_a));
        const float y1 = relu6f(fmaf(d1, s_b, o_b));
        const float y2 = relu6f(fmaf(d2, s_a, o_a));
        const float y3 = relu6f(fmaf(d3, s_b, o_b));
        *reinterpret_cast<unsigned*>(sx + rlo * XST + c0) = f2toh2(y0, y1);
        *reinterpret_cast<unsigned*>(sx + rhi * XST + c0) = f2toh2(y2, y3);
    }
    __syncthreads();

    // coalesced store: 64 rows x 24 uint4
    uint4* xb = reinterpret_cast<uint4*>(g_x1);
    const uint4* sxb = reinterpret_cast<const uint4*>(sx);
#pragma unroll
    for (int i = tid; i < 64 * 24; i += 768) {
        const int r = i / 24, ch = i % 24;
        const int row = r0 + r;
        if (row < N) xb[(size_t)row * 24 + ch] = sxb[r * 26 + ch];
    }
}

// ---------------------------------------------------------------------------
// Kernel 2: depthwise sparse conv (9-way gather) + BN2 + relu6 -> g_z (fp16)
// Thread = (4 rows, one 8-channel chunk). 9 independent LDG.128 gathers per
// (row,chunk) give MLP to hide L2 latency; x1 is L2-resident.
// ---------------------------------------------------------------------------
__global__ void __launch_bounds__(256) k_dw(
    const int* __restrict__ nbr, const float* __restrict__ W2,
    const float* __restrict__ g2, const float* __restrict__ b2,
    const float* __restrict__ m2, const float* __restrict__ v2,
    int N)
{
    __shared__ __align__(16) float W2s[KOFF * HID];
    __shared__ __align__(16) float s2s[HID];
    __shared__ __align__(16) float c2s[HID];

    const int tid = threadIdx.x;
    for (int t = tid; t < KOFF * HID; t += 256) W2s[t] = W2[t];
    for (int t = tid; t < HID; t += 256) {
        const float s = g2[t] * rsqrtf(v2[t] + EPSV);
        s2s[t] = s;
        c2s[t] = b2[t] - m2[t] * s;
    }
    __syncthreads();

    const long long gidx = (long long)blockIdx.x * 256 + tid;
    const int chunk = (int)(gidx % 24);
    const int rg    = (int)(gidx / 24);
    const int r0    = rg * 4;
    if (r0 >= N) return;
    const int nrows = (N - r0 < 4) ? (N - r0) : 4;
    const int ch8 = chunk * 8;

    int idxs[4][KOFF];
#pragma unroll
    for (int r = 0; r < 4; r++)
#pragma unroll
        for (int k = 0; k < KOFF; k++)
            idxs[r][k] = (r < nrows) ? nbr[(r0 + r) * KOFF + k] : -1;

    float2 acc[4][4];
#pragma unroll
    for (int r = 0; r < 4; r++)
#pragma unroll
        for (int j = 0; j < 4; j++) acc[r][j] = make_float2(0.0f, 0.0f);

    const uint4* xb = reinterpret_cast<const uint4*>(g_x1);

#pragma unroll
    for (int k = 0; k < KOFF; k++) {
        const float4 wA = *reinterpret_cast<const float4*>(W2s + k * HID + ch8);
        const float4 wB = *reinterpret_cast<const float4*>(W2s + k * HID + ch8 + 4);
#pragma unroll
        for (int r = 0; r < 4; r++) {
            const int id = idxs[r][k];
            if (id >= 0) {
                const uint4 v = xb[id * 24 + chunk];
                const float2 f0 = h2tof2(v.x);
                const float2 f1 = h2tof2(v.y);
                const float2 f2 = h2tof2(v.z);
                const float2 f3 = h2tof2(v.w);
                acc[r][0].x = fmaf(f0.x, wA.x, acc[r][0].x);
                acc[r][0].y = fmaf(f0.y, wA.y, acc[r][0].y);
                acc[r][1].x = fmaf(f1.x, wA.z, acc[r][1].x);
                acc[r][1].y = fmaf(f1.y, wA.w, acc[r][1].y);
                acc[r][2].x = fmaf(f2.x, wB.x, acc[r][2].x);
                acc[r][2].y = fmaf(f2.y, wB.y, acc[r][2].y);
                acc[r][3].x = fmaf(f3.x, wB.z, acc[r][3].x);
                acc[r][3].y = fmaf(f3.y, wB.w, acc[r][3].y);
            }
        }
    }

    const float4 sA = *reinterpret_cast<const float4*>(s2s + ch8);
    const float4 sB = *reinterpret_cast<const float4*>(s2s + ch8 + 4);
    const float4 cA = *reinterpret_cast<const float4*>(c2s + ch8);
    const float4 cB = *reinterpret_cast<const float4*>(c2s + ch8 + 4);
    uint4* zb = reinterpret_cast<uint4*>(g_z);

#pragma unroll
    for (int r = 0; r < 4; r++) {
        if (r < nrows) {
            const float y0 = relu6f(fmaf(acc[r][0].x, sA.x, cA.x));
            const float y1 = relu6f(fmaf(acc[r][0].y, sA.y, cA.y));
            const float y2 = relu6f(fmaf(acc[r][1].x, sA.z, cA.z));
            const float y3 = relu6f(fmaf(acc[r][1].y, sA.w, cA.w));
            const float y4 = relu6f(fmaf(acc[r][2].x, sB.x, cB.x));
            const float y5 = relu6f(fmaf(acc[r][2].y, sB.y, cB.y));
            const float y6 = relu6f(fmaf(acc[r][3].x, sB.z, cB.z));
            const float y7 = relu6f(fmaf(acc[r][3].y, sB.w, cB.w));
            uint4 o;
            o.x = f2toh2(y0, y1);
            o.y = f2toh2(y2, y3);
            o.z = f2toh2(y4, y5);
            o.w = f2toh2(y6, y7);
            zb[(r0 + r) * 24 + chunk] = o;
        }
    }
}

// ---------------------------------------------------------------------------
// Kernel 3 (MMA): project 1x1 conv (z @ W3) + BN3 + residual -> out (fp32)
// Block = 512 thr = 16 warps; warp w: n-tile j=w&3 (8 cols), row-subtile
// rs=w>>2 (16 rows). 64-row z tile staged fp16 in smem (stride 200 halves =
// 100 words, 100 mod 32 = 4 -> conflict-free fragment loads).
// K=192 -> 12 k-steps; W3 B-fragments in 24 regs/thread.
// ---------------------------------------------------------------------------
#define ZST 200   // z smem row stride (halves) = 25 uint4 — conflict-free

__global__ void __launch_bounds__(512) k_proj(
    const float* __restrict__ W3, const float* __restrict__ feats,
    const float* __restrict__ g3, const float* __restrict__ b3,
    const float* __restrict__ m3, const float* __restrict__ v3,
    float* __restrict__ out, int N)
{
    __shared__ __align__(16) __half zs[64 * ZST];

    const int tid  = threadIdx.x;
    const int w    = tid >> 5;
    const int lane = tid & 31;
    const int g    = lane >> 2;
    const int t    = lane & 3;
    const int j    = w & 3;            // n-tile
    const int rs   = w >> 2;           // row subtile
    const int colb = 8 * j;
    const int c0   = colb + 2 * t;
    const int c1   = c0 + 1;

    // B fragments for all 12 k-steps
    unsigned bf[12][2];
#pragma unroll
    for (int s = 0; s < 12; s++) {
        const int col = colb + g;
        const int k0 = 16 * s + 2 * t;
        bf[s][0] = packh(__float2half(W3[(k0)     * COUT + col]),
                         __float2half(W3[(k0 + 1) * COUT + col]));
        bf[s][1] = packh(__float2half(W3[(k0 + 8) * COUT + col]),
                         __float2half(W3[(k0 + 9) * COUT + col]));
    }
    const float s_a = g3[c0] * rsqrtf(v3[c0] + EPSV);
    const float o_a = b3[c0] - m3[c0] * s_a;
    const float s_b = g3[c1] * rsqrtf(v3[c1] + EPSV);
    const float o_b = b3[c1] - m3[c1] * s_b;

    const int r0 = blockIdx.x * 64;

    // stage z tile: 64 rows x 24 uint4 (coalesced), ring stride 25
    const uint4* zg = reinterpret_cast<const uint4*>(g_z);
    uint4* zsb = reinterpret_cast<uint4*>(zs);
#pragma unroll
    for (int i = tid; i < 64 * 24; i += 512) {
        const int r = i / 24, ch = i % 24;
        const int row = r0 + r;
        uint4 v;
        if (row < N) v = zg[(size_t)row * 24 + ch];
        else         v = make_uint4(0u, 0u, 0u, 0u);
        zsb[r * 25 + ch] = v;
    }
    __syncthreads();

    float d0 = 0.f, d1 = 0.f, d2 = 0.f, d3 = 0.f;
    const __half* base = zs + (rs * 16) * ZST;
#pragma unroll
    for (int s = 0; s < 12; s++) {
        const int ko = 2 * t + 16 * s;
        unsigned a0 = *reinterpret_cast<const unsigned*>(base + g * ZST + ko);
        unsigned a1 = *reinterpret_cast<const unsigned*>(base + (g + 8) * ZST + ko);
        unsigned a2 = *reinterpret_cast<const unsigned*>(base + g * ZST + ko + 8);
        unsigned a3 = *reinterpret_cast<const unsigned*>(base + (g + 8) * ZST + ko + 8);
        mma16816(d0, d1, d2, d3, a0, a1, a2, a3, bf[s][0], bf[s][1]);
    }

    // epilogue: BN3 + residual, fp32 out
    const int rlo = r0 + rs * 16 + g;
    const int rhi = rlo + 8;
    if (rlo < N) {
        const float2 fi = *reinterpret_cast<const float2*>(feats + rlo * COUT + c0);
        float2 o;
        o.x = fmaf(d0, s_a, o_a) + fi.x;
        o.y = fmaf(d1, s_b, o_b) + fi.y;
        *reinterpret_cast<float2*>(out + rlo * COUT + c0) = o;
    }
    if (rhi < N) {
        const float2 fi = *reinterpret_cast<const float2*>(feats + rhi * COUT + c0);
        float2 o;
        o.x = fmaf(d2, s_a, o_a) + fi.x;
        o.y = fmaf(d3, s_b, o_b) + fi.y;
        *reinterpret_cast<float2*>(out + rhi * COUT + c0) = o;
    }
}

// ---------------------------------------------------------------------------
extern "C" void kernel_launch(void* const* d_in, const int* in_sizes, int n_in,
                              void* d_out, int out_size)
{
    const float* feats = (const float*)d_in[0];
    const int*   nbr   = (const int*)  d_in[1];
    const float* W1    = (const float*)d_in[2];
    const float* W2    = (const float*)d_in[3];
    const float* W3    = (const float*)d_in[4];
    const float* g1 = (const float*)d_in[5],  *b1 = (const float*)d_in[6];
    const float* m1 = (const float*)d_in[7],  *v1 = (const float*)d_in[8];
    const float* g2 = (const float*)d_in[9],  *b2 = (const float*)d_in[10];
    const float* m2 = (const float*)d_in[11], *v2 = (const float*)d_in[12];
    const float* g3 = (const float*)d_in[13], *b3 = (const float*)d_in[14];
    const float* m3 = (const float*)d_in[15], *v3 = (const float*)d_in[16];
    float* out = (float*)d_out;

    int N = in_sizes[0] / CIN;
    if (N > MAXN) N = MAXN;

    const int tiles = (N + 63) / 64;

    // K1: expand (MMA)
    k_expand<<<tiles, 768>>>(feats, W1, g1, b1, m1, v1, N);

    // K2: depthwise gather
    const long long items = (long long)((N + 3) / 4) * 24;
    const int grid2 = (int)((items + 255) / 256);
    k_dw<<<grid2, 256>>>(nbr, W2, g2, b2, m2, v2, N);

    // K3: project + residual (MMA)
    k_proj<<<tiles, 512>>>(W3, feats, g3, b3, m3, v3, out, N);
}